// round 10
// baseline (speedup 1.0000x reference)
#include <cuda_runtime.h>
#include <cuda_bf16.h>
#include <math.h>

// T=2048 tokens, H=2048 hidden, V=32000 vocab, E=16 experts, top-2.
// Inputs: hidden_states (T*H f32), gate_w (16*H f32), expert_biases (16*V f32).
// Output: bias (T*V f32) then aux_loss (1 f32).

#define NUM_E 16
#define MAX_T 8192

__device__ float  g_probs[MAX_T * NUM_E];   // softmax probs per token
__device__ float4 g_meta[MAX_T];            // (w0, w1, bitcast i0, bitcast i1)

// ---------------------------------------------------------------------------
// Gate: logits + softmax + top-2. Warp-per-TOKEN-PAIR: each g float4 load
// feeds 8 FFMA (2 tokens x f4-dot) -> halves gate_w L1 traffic (the measured
// bottleneck at 1 token/warp). h loads front-batched 8-wide per chunk (MLP=8).
// Block = 128 thr = 4 warps = 8 tokens; grid = T/8 = 256.
// ---------------------------------------------------------------------------
__global__ __launch_bounds__(128) void gate_kernel(
    const float* __restrict__ hidden,
    const float* __restrict__ gate_w,
    int H)
{
    const int tid  = threadIdx.x;
    const int lane = tid & 31;
    const int warp = tid >> 5;
    const int Hf4  = H >> 2;                 // 512
    const int tok0 = (blockIdx.x * 4 + warp) * 2;

    const float4* __restrict__ gf4  = (const float4*)gate_w;
    const float4* __restrict__ hrow0 = (const float4*)hidden + (size_t)tok0 * Hf4;
    const float4* __restrict__ hrow1 = hrow0 + Hf4;

    float acc0[NUM_E], acc1[NUM_E];
    #pragma unroll
    for (int e = 0; e < NUM_E; e++) { acc0[e] = 0.0f; acc1[e] = 0.0f; }

    // lane covers positions lane + 32*j, j=0..15, in 4 chunks of 4
    #pragma unroll
    for (int c = 0; c < 4; c++) {
        float4 h0[4], h1[4];
        #pragma unroll
        for (int jj = 0; jj < 4; jj++) {
            const int pos = lane + (c * 4 + jj) * 32;
            h0[jj] = hrow0[pos];             // 8 independent loads up-front
            h1[jj] = hrow1[pos];
        }
        #pragma unroll
        for (int jj = 0; jj < 4; jj++) {
            const int pos = lane + (c * 4 + jj) * 32;
            #pragma unroll
            for (int e = 0; e < NUM_E; e++) {
                float4 g = __ldg(&gf4[(size_t)e * Hf4 + pos]);
                acc0[e] += h0[jj].x*g.x + h0[jj].y*g.y + h0[jj].z*g.z + h0[jj].w*g.w;
                acc1[e] += h1[jj].x*g.x + h1[jj].y*g.y + h1[jj].z*g.z + h1[jj].w*g.w;
            }
        }
    }

    // butterfly: all lanes end with complete sums for both tokens
    #pragma unroll
    for (int e = 0; e < NUM_E; e++) {
        float v0 = acc0[e], v1 = acc1[e];
        #pragma unroll
        for (int s = 16; s > 0; s >>= 1) {
            v0 += __shfl_xor_sync(0xffffffffu, v0, s);
            v1 += __shfl_xor_sync(0xffffffffu, v1, s);
        }
        acc0[e] = v0; acc1[e] = v1;
    }

    // lane 0 finishes tok0, lane 1 finishes tok1 (in parallel)
    if (lane < 2) {
        const int tok = tok0 + lane;
        float l[NUM_E];
        #pragma unroll
        for (int e = 0; e < NUM_E; e++) l[e] = (lane == 0) ? acc0[e] : acc1[e];

        float mx = -1e30f;
        #pragma unroll
        for (int e = 0; e < NUM_E; e++) mx = fmaxf(mx, l[e]);
        float p[NUM_E];
        float sum = 0.0f;
        #pragma unroll
        for (int e = 0; e < NUM_E; e++) { p[e] = expf(l[e] - mx); sum += p[e]; }
        float inv = 1.0f / sum;

        int   i0 = 0, i1 = -1;
        float p0 = -1.0f, p1 = -1.0f;
        float pr[NUM_E];
        #pragma unroll
        for (int e = 0; e < NUM_E; e++) {
            float pe = p[e] * inv;
            pr[e] = pe;
            if (pe > p0)      { p1 = p0; i1 = i0; p0 = pe; i0 = e; }
            else if (pe > p1) { p1 = pe; i1 = e; }
        }
        float4* probs4 = (float4*)&g_probs[(size_t)tok * NUM_E];
        #pragma unroll
        for (int c = 0; c < 4; c++)
            probs4[c] = make_float4(pr[c*4], pr[c*4+1], pr[c*4+2], pr[c*4+3]);

        float s2 = p0 + p1;
        float4 m;
        m.x = p0 / s2;
        m.y = p1 / s2;
        m.z = __int_as_float(i0);
        m.w = __int_as_float(i1);
        g_meta[tok] = m;
    }
}

// ---------------------------------------------------------------------------
// Bias = w0*B[i0] + w1*B[i1] (262 MB stores, write-bound, at DRAM floor:
// 2048B line-aligned chunks + streaming stores). Block (0,0) additionally
// computes the aux loss from g_probs — hidden under the other blocks' work.
// ---------------------------------------------------------------------------
#define CHUNK_F4 128          // 512 floats = 2048 B per expert per chunk
#define TOK_GRP  128

__global__ __launch_bounds__(256) void bias_kernel(
    const float* __restrict__ biases,
    float* __restrict__ out,
    float* __restrict__ out_aux,
    int V, int T)
{
    __shared__ float4 sB[NUM_E][CHUNK_F4];   // 32 KB
    __shared__ float4 smeta[TOK_GRP];        // 2 KB
    __shared__ float4 s4[256];               // 4 KB (aux reduction, block 0,0)
    __shared__ float4 su4[4];

    const int tid   = threadIdx.x;
    const int lane  = tid & 31;
    const int warp  = tid >> 5;
    const int Vf4   = V >> 2;                       // 8000
    const int vbase = blockIdx.x * CHUNK_F4;        // 2048B-aligned
    const int clen  = min(CHUNK_F4, Vf4 - vbase);   // 128 or 64 (tail)
    const int tbase = blockIdx.y * TOK_GRP;

    const float4* __restrict__ bf4 = (const float4*)biases;
    float4* __restrict__ of4 = (float4*)out;

    for (int i = tid; i < NUM_E * CHUNK_F4; i += 256) {
        int e = i >> 7, p = i & (CHUNK_F4 - 1);
        if (p < clen) sB[e][p] = bf4[(size_t)e * Vf4 + vbase + p];
    }
    if (tid < TOK_GRP) smeta[tid] = g_meta[tbase + tid];
    __syncthreads();

    // warp-per-token, lane-contiguous 16B streaming stores
    for (int t = warp; t < TOK_GRP; t += 8) {
        float4 m = smeta[t];
        const float w0 = m.x, w1 = m.y;
        const int i0 = __float_as_int(m.z);
        const int i1 = __float_as_int(m.w);
        float4* __restrict__ orow = &of4[(size_t)(tbase + t) * Vf4 + vbase];
        #pragma unroll 4
        for (int p = lane; p < clen; p += 32) {
            float4 a = sB[i0][p];
            float4 b = sB[i1][p];
            float4 r;
            r.x = w0 * a.x + w1 * b.x;
            r.y = w0 * a.y + w1 * b.y;
            r.z = w0 * a.z + w1 * b.z;
            r.w = w0 * a.w + w1 * b.w;
            __stcs(&orow[p], r);
        }
    }

    // ---- aux loss, computed only by block (0,0), deterministic ----
    if (blockIdx.x == 0 && blockIdx.y == 0) {
        const int e4 = tid & 3;
        const int c  = tid >> 2;
        const float4* __restrict__ probs4 = (const float4*)g_probs;

        float4 sum = make_float4(0.f, 0.f, 0.f, 0.f);
        for (int t = c; t < T; t += 64) {
            float4 v = probs4[(size_t)t * 4 + e4];
            sum.x += v.x; sum.y += v.y; sum.z += v.z; sum.w += v.w;
        }
        s4[tid] = sum;
        __syncthreads();

        if (tid < 4) {
            float4 u = make_float4(0.f, 0.f, 0.f, 0.f);
            #pragma unroll
            for (int cc = 0; cc < 64; cc++) {
                float4 v = s4[cc * 4 + tid];
                u.x += v.x; u.y += v.y; u.z += v.z; u.w += v.w;
            }
            su4[tid] = u;
        }
        __syncthreads();

        if (tid == 0) {
            float invT = 1.0f / (float)T;
            float aux = 0.0f;
            #pragma unroll
            for (int q = 0; q < 4; q++) {
                float4 u = su4[q];
                float a = u.x * invT, b = u.y * invT;
                float cc = u.z * invT, d = u.w * invT;
                aux += a * logf(a) + b * logf(b) + cc * logf(cc) + d * logf(d);
            }
            out_aux[0] = aux * (float)NUM_E;
        }
    }
}

// ---------------------------------------------------------------------------
extern "C" void kernel_launch(void* const* d_in, const int* in_sizes, int n_in,
                              void* d_out, int out_size)
{
    const float* hidden = (const float*)d_in[0];
    const float* gate_w = (const float*)d_in[1];
    const float* biases = (const float*)d_in[2];
    float* out = (float*)d_out;

    const int H = in_sizes[1] / NUM_E;         // 2048
    const int T = in_sizes[0] / H;             // 2048
    const int V = in_sizes[2] / NUM_E;         // 32000

    // 1) gate: warp-per-token-pair
    gate_kernel<<<T / 8, 128>>>(hidden, gate_w, H);

    // 2) bias gather+blend (+ aux loss in block (0,0))
    const int nchunks = (V / 4 + CHUNK_F4 - 1) / CHUNK_F4;   // 63
    dim3 grid(nchunks, T / TOK_GRP);                         // (63, 16)
    bias_kernel<<<grid, 256>>>(biases, out, out + (size_t)T * V, V, T);
}

// round 11
// speedup vs baseline: 1.2204x; 1.2204x over previous
#include <cuda_runtime.h>
#include <cuda_bf16.h>
#include <math.h>

// T=2048 tokens, H=2048 hidden, V=32000 vocab, E=16 experts, top-2.
// Inputs: hidden_states (T*H f32), gate_w (16*H f32), expert_biases (16*V f32).
// Output: bias (T*V f32) then aux_loss (1 f32).

#define NUM_E 16
#define MAX_T 8192

__device__ float  g_probs[MAX_T * NUM_E];   // softmax probs per token
__device__ float4 g_meta[MAX_T];            // (w0, w1, bitcast i0, bitcast i1)

// ---------------------------------------------------------------------------
// Gate: warp = (token-pair) x (H-half). 2048 warps total (grid=256, 256 thr):
// same occupancy as the best 1-token/warp gate, but each gate_w float4 feeds
// 8 FFMA (2 tokens) -> gate_w L1 traffic halved. h front-batched 8 loads/chunk.
// Halves combine via 1KB smem; 8 tokens/block finished by 8 threads.
// ---------------------------------------------------------------------------
__global__ __launch_bounds__(256) void gate_kernel(
    const float* __restrict__ hidden,
    const float* __restrict__ gate_w,
    int H)
{
    const int tid  = threadIdx.x;
    const int lane = tid & 31;
    const int warp = tid >> 5;
    const int pl   = warp & 3;          // pair 0..3 within block
    const int hh   = warp >> 2;         // H half 0/1
    const int Hf4  = H >> 2;            // 512
    const int halfHf4 = Hf4 >> 1;       // 256
    const int tok0 = blockIdx.x * 8 + pl * 2;

    const float4* __restrict__ gf4 = (const float4*)gate_w;
    const float4* __restrict__ hrow0 =
        (const float4*)hidden + (size_t)tok0 * Hf4 + hh * halfHf4;
    const float4* __restrict__ hrow1 = hrow0 + Hf4;
    const float4* __restrict__ gbase = gf4 + hh * halfHf4;

    __shared__ float red[8][2][NUM_E];  // [warp][token-in-pair][expert]

    float acc0[NUM_E], acc1[NUM_E];
    #pragma unroll
    for (int e = 0; e < NUM_E; e++) { acc0[e] = 0.0f; acc1[e] = 0.0f; }

    // lane covers positions lane + 32*j, j=0..7, in 2 chunks of 4
    #pragma unroll
    for (int c = 0; c < 2; c++) {
        float4 h0[4], h1[4];
        #pragma unroll
        for (int jj = 0; jj < 4; jj++) {
            const int pos = lane + (c * 4 + jj) * 32;
            h0[jj] = hrow0[pos];        // 8 independent loads up-front
            h1[jj] = hrow1[pos];
        }
        #pragma unroll
        for (int jj = 0; jj < 4; jj++) {
            const int pos = lane + (c * 4 + jj) * 32;
            #pragma unroll
            for (int e = 0; e < NUM_E; e++) {
                float4 g = __ldg(&gbase[(size_t)e * Hf4 + pos]);
                acc0[e] += h0[jj].x*g.x + h0[jj].y*g.y + h0[jj].z*g.z + h0[jj].w*g.w;
                acc1[e] += h1[jj].x*g.x + h1[jj].y*g.y + h1[jj].z*g.z + h1[jj].w*g.w;
            }
        }
    }

    // butterfly both tokens; lane 0 stores the 32 partials for this warp
    #pragma unroll
    for (int e = 0; e < NUM_E; e++) {
        float v0 = acc0[e], v1 = acc1[e];
        #pragma unroll
        for (int s = 16; s > 0; s >>= 1) {
            v0 += __shfl_xor_sync(0xffffffffu, v0, s);
            v1 += __shfl_xor_sync(0xffffffffu, v1, s);
        }
        if (lane == 0) { red[warp][0][e] = v0; red[warp][1][e] = v1; }
    }
    __syncthreads();

    // 8 threads finish the block's 8 tokens
    if (tid < 8) {
        const int tpl = tid >> 1;       // pair 0..3
        const int ti  = tid & 1;        // token within pair
        const int tok = blockIdx.x * 8 + tpl * 2 + ti;

        float l[NUM_E];
        #pragma unroll
        for (int e = 0; e < NUM_E; e++)
            l[e] = red[tpl][ti][e] + red[tpl + 4][ti][e];

        float mx = -1e30f;
        #pragma unroll
        for (int e = 0; e < NUM_E; e++) mx = fmaxf(mx, l[e]);
        float p[NUM_E];
        float sum = 0.0f;
        #pragma unroll
        for (int e = 0; e < NUM_E; e++) { p[e] = expf(l[e] - mx); sum += p[e]; }
        float inv = 1.0f / sum;

        int   i0 = 0, i1 = -1;
        float p0 = -1.0f, p1 = -1.0f;
        float pr[NUM_E];
        #pragma unroll
        for (int e = 0; e < NUM_E; e++) {
            float pe = p[e] * inv;
            pr[e] = pe;
            if (pe > p0)      { p1 = p0; i1 = i0; p0 = pe; i0 = e; }
            else if (pe > p1) { p1 = pe; i1 = e; }
        }
        float4* probs4 = (float4*)&g_probs[(size_t)tok * NUM_E];
        #pragma unroll
        for (int c = 0; c < 4; c++)
            probs4[c] = make_float4(pr[c*4], pr[c*4+1], pr[c*4+2], pr[c*4+3]);

        float s2 = p0 + p1;
        float4 m;
        m.x = p0 / s2;
        m.y = p1 / s2;
        m.z = __int_as_float(i0);
        m.w = __int_as_float(i1);
        g_meta[tok] = m;
    }
}

// ---------------------------------------------------------------------------
// Bias = w0*B[i0] + w1*B[i1] (262 MB stores, write-bound, at DRAM floor:
// 2048B line-aligned chunks + streaming stores). Block (0,0) additionally
// computes the aux loss from g_probs — hidden under the other blocks' work.
// (Byte-identical to the measured-best R9 version.)
// ---------------------------------------------------------------------------
#define CHUNK_F4 128          // 512 floats = 2048 B per expert per chunk
#define TOK_GRP  128

__global__ __launch_bounds__(256) void bias_kernel(
    const float* __restrict__ biases,
    float* __restrict__ out,
    float* __restrict__ out_aux,
    int V, int T)
{
    __shared__ float4 sB[NUM_E][CHUNK_F4];   // 32 KB
    __shared__ float4 smeta[TOK_GRP];        // 2 KB
    __shared__ float4 s4[256];               // 4 KB (aux reduction, block 0,0)
    __shared__ float4 su4[4];

    const int tid   = threadIdx.x;
    const int lane  = tid & 31;
    const int warp  = tid >> 5;
    const int Vf4   = V >> 2;                       // 8000
    const int vbase = blockIdx.x * CHUNK_F4;        // 2048B-aligned
    const int clen  = min(CHUNK_F4, Vf4 - vbase);   // 128 or 64 (tail)
    const int tbase = blockIdx.y * TOK_GRP;

    const float4* __restrict__ bf4 = (const float4*)biases;
    float4* __restrict__ of4 = (float4*)out;

    for (int i = tid; i < NUM_E * CHUNK_F4; i += 256) {
        int e = i >> 7, p = i & (CHUNK_F4 - 1);
        if (p < clen) sB[e][p] = bf4[(size_t)e * Vf4 + vbase + p];
    }
    if (tid < TOK_GRP) smeta[tid] = g_meta[tbase + tid];
    __syncthreads();

    // warp-per-token, lane-contiguous 16B streaming stores
    for (int t = warp; t < TOK_GRP; t += 8) {
        float4 m = smeta[t];
        const float w0 = m.x, w1 = m.y;
        const int i0 = __float_as_int(m.z);
        const int i1 = __float_as_int(m.w);
        float4* __restrict__ orow = &of4[(size_t)(tbase + t) * Vf4 + vbase];
        #pragma unroll 4
        for (int p = lane; p < clen; p += 32) {
            float4 a = sB[i0][p];
            float4 b = sB[i1][p];
            float4 r;
            r.x = w0 * a.x + w1 * b.x;
            r.y = w0 * a.y + w1 * b.y;
            r.z = w0 * a.z + w1 * b.z;
            r.w = w0 * a.w + w1 * b.w;
            __stcs(&orow[p], r);
        }
    }

    // ---- aux loss, computed only by block (0,0), deterministic ----
    if (blockIdx.x == 0 && blockIdx.y == 0) {
        const int e4 = tid & 3;
        const int c  = tid >> 2;
        const float4* __restrict__ probs4 = (const float4*)g_probs;

        float4 sum = make_float4(0.f, 0.f, 0.f, 0.f);
        for (int t = c; t < T; t += 64) {
            float4 v = probs4[(size_t)t * 4 + e4];
            sum.x += v.x; sum.y += v.y; sum.z += v.z; sum.w += v.w;
        }
        s4[tid] = sum;
        __syncthreads();

        if (tid < 4) {
            float4 u = make_float4(0.f, 0.f, 0.f, 0.f);
            #pragma unroll
            for (int cc = 0; cc < 64; cc++) {
                float4 v = s4[cc * 4 + tid];
                u.x += v.x; u.y += v.y; u.z += v.z; u.w += v.w;
            }
            su4[tid] = u;
        }
        __syncthreads();

        if (tid == 0) {
            float invT = 1.0f / (float)T;
            float aux = 0.0f;
            #pragma unroll
            for (int q = 0; q < 4; q++) {
                float4 u = su4[q];
                float a = u.x * invT, b = u.y * invT;
                float cc = u.z * invT, d = u.w * invT;
                aux += a * logf(a) + b * logf(b) + cc * logf(cc) + d * logf(d);
            }
            out_aux[0] = aux * (float)NUM_E;
        }
    }
}

// ---------------------------------------------------------------------------
extern "C" void kernel_launch(void* const* d_in, const int* in_sizes, int n_in,
                              void* d_out, int out_size)
{
    const float* hidden = (const float*)d_in[0];
    const float* gate_w = (const float*)d_in[1];
    const float* biases = (const float*)d_in[2];
    float* out = (float*)d_out;

    const int H = in_sizes[1] / NUM_E;         // 2048
    const int T = in_sizes[0] / H;             // 2048
    const int V = in_sizes[2] / NUM_E;         // 32000

    // 1) gate: warp = (token-pair) x (H-half), 2048 warps
    gate_kernel<<<T / 8, 256>>>(hidden, gate_w, H);

    // 2) bias gather+blend (+ aux loss in block (0,0))
    const int nchunks = (V / 4 + CHUNK_F4 - 1) / CHUNK_F4;   // 63
    dim3 grid(nchunks, T / TOK_GRP);                         // (63, 16)
    bias_kernel<<<grid, 256>>>(biases, out, out + (size_t)T * V, V, T);
}